// round 6
// baseline (speedup 1.0000x reference)
#include <cuda_runtime.h>
#include <math.h>

// SGNS loss (VOCAB=100000, D=128, B=4096, C=10, N_NEGS=20):
//   iv = emb_i[iword]                      [B,128]
//   oscore_c = <emb_o[owords_bc], iv_b>    (10 per b)
//   nscore_k = -<emb_o[nwords_bk], iv_b>   (200 per b)
//   loss = -mean_b( (1/C) * [ sum_c logsig(oscore_c) + sum_k logsig(nscore_k) ] )

#define BATCH 4096
#define CCTX 10
#define NNEG 200
#define NROWS 210        // 10 positives + 200 negatives
#define NROWS_PAD 224    // 8 warps * ILP4 * 7 iterations (dummy idx 0 in pad)
#define NITER 7
#define DIM 128

__device__ float g_partials[BATCH];

__device__ __forceinline__ float log_sigmoid(float x) {
    // stable: min(x,0) - log1p(exp(-|x|))
    return fminf(x, 0.0f) - log1pf(__expf(-fabsf(x)));
}

__global__ __launch_bounds__(256) void sgns_main_kernel(
    const float* __restrict__ emb_i,
    const float* __restrict__ emb_o,
    const int*   __restrict__ iword,
    const int*   __restrict__ owords,
    const int*   __restrict__ nwords)
{
    const int b    = blockIdx.x;
    const int tid  = threadIdx.x;
    const int lane = tid & 31;
    const int w    = tid >> 5;           // 8 warps

    __shared__ float4 s_iv[32];
    __shared__ int    s_idx[NROWS_PAD];  // [0,CCTX): pos; [CCTX,NROWS): neg; pad: 0
    __shared__ float  s_warp[8];

    if (tid < 32) {
        const float4* ivrow = reinterpret_cast<const float4*>(
            emb_i + (long long)iword[b] * DIM);
        s_iv[tid] = __ldg(&ivrow[tid]);
    }
    if (tid < NROWS_PAD) {
        int v = 0;
        if (tid < CCTX)        v = __ldg(&owords[b * CCTX + tid]);
        else if (tid < NROWS)  v = __ldg(&nwords[b * NNEG + (tid - CCTX)]);
        s_idx[tid] = v;
    }
    __syncthreads();

    const float4 iv = s_iv[lane];        // lane l owns elements [4l, 4l+4)

    float acc = 0.0f;

    // Depth-2 software pipeline over 7 branch-free ILP-4 iterations.
    // Rows of iteration j (for this warp): w + 32*j + {0,8,16,24}.
    float4 cur[4], nxt[4];

    #pragma unroll
    for (int u = 0; u < 4; u++) {
        const int idx = s_idx[w + 8 * u];
        cur[u] = __ldg(&reinterpret_cast<const float4*>(
                     emb_o + (long long)idx * DIM)[lane]);
    }

    #pragma unroll
    for (int j = 0; j < NITER; j++) {
        const int r0 = w + 32 * j;

        // Issue next iteration's loads BEFORE reducing this one.
        if (j + 1 < NITER) {
            #pragma unroll
            for (int u = 0; u < 4; u++) {
                const int idx = s_idx[r0 + 32 + 8 * u];
                nxt[u] = __ldg(&reinterpret_cast<const float4*>(
                             emb_o + (long long)idx * DIM)[lane]);
            }
        }

        float d[4];
        #pragma unroll
        for (int u = 0; u < 4; u++)
            d[u] = cur[u].x * iv.x + cur[u].y * iv.y +
                   cur[u].z * iv.z + cur[u].w * iv.w;

        // 4 independent butterfly chains, interleaved; next loads in flight.
        #pragma unroll
        for (int o = 16; o > 0; o >>= 1) {
            #pragma unroll
            for (int u = 0; u < 4; u++)
                d[u] += __shfl_xor_sync(0xffffffffu, d[u], o);
        }

        #pragma unroll
        for (int u = 0; u < 4; u++) {
            const int r = r0 + 8 * u;
            const float sgn  = (r < CCTX)  ? 1.0f : -1.0f;
            const float mask = (r < NROWS) ? 1.0f : 0.0f;
            acc += mask * log_sigmoid(sgn * d[u]);
        }

        #pragma unroll
        for (int u = 0; u < 4; u++) cur[u] = nxt[u];
    }

    if (lane == 0) s_warp[w] = acc;
    __syncthreads();

    if (tid == 0) {
        float s = 0.0f;
        #pragma unroll
        for (int i = 0; i < 8; i++) s += s_warp[i];
        g_partials[b] = s * (1.0f / (float)CCTX);
    }
}

__global__ __launch_bounds__(1024) void sgns_reduce_kernel(float* __restrict__ out)
{
    __shared__ float s[1024];
    const int t = threadIdx.x;
    float v = g_partials[t] + g_partials[t + 1024] +
              g_partials[t + 2048] + g_partials[t + 3072];
    s[t] = v;
    __syncthreads();
    #pragma unroll
    for (int o = 512; o > 0; o >>= 1) {
        if (t < o) s[t] += s[t + o];
        __syncthreads();
    }
    if (t == 0) out[0] = -s[0] * (1.0f / (float)BATCH);
}

extern "C" void kernel_launch(void* const* d_in, const int* in_sizes, int n_in,
                              void* d_out, int out_size)
{
    const float* emb_i  = (const float*)d_in[0];
    const float* emb_o  = (const float*)d_in[1];
    const int*   iword  = (const int*)  d_in[2];
    const int*   owords = (const int*)  d_in[3];
    const int*   nwords = (const int*)  d_in[4];
    float* out = (float*)d_out;

    sgns_main_kernel<<<BATCH, 256>>>(emb_i, emb_o, iword, owords, nwords);
    sgns_reduce_kernel<<<1, 1024>>>(out);
}

// round 10
// speedup vs baseline: 1.2749x; 1.2749x over previous
#include <cuda_runtime.h>
#include <math.h>

// SGNS loss (VOCAB=100000, D=128, B=4096, C=10, N_NEGS=20):
//   iv = emb_i[iword]                      [B,128]
//   oscore_c = <emb_o[owords_bc], iv_b>    (10 per b)
//   nscore_k = -<emb_o[nwords_bk], iv_b>   (200 per b)
//   loss = -mean_b( (1/C) * [ sum_c logsig(oscore_c) + sum_k logsig(nscore_k) ] )
// Single fused kernel: per-block partials + last-block-done final reduction.

#define BATCH 4096
#define CCTX 10
#define NNEG 200
#define NROWS 210        // 10 positives + 200 negatives
#define NROWS_PAD 224    // 8 warps * ILP4 * 7 iterations (dummy idx 0 in pad)
#define NITER 7
#define DIM 128

__device__ float        g_partials[BATCH];
__device__ unsigned int g_done;      // zero-init at load; reset by tail block

__device__ __forceinline__ float log_sigmoid(float x) {
    // stable: min(x,0) - log(1 + exp(-|x|));  arg of log in (1,2] -> __logf ok
    return fminf(x, 0.0f) - __logf(1.0f + __expf(-fabsf(x)));
}

__global__ __launch_bounds__(256) void sgns_fused_kernel(
    const float* __restrict__ emb_i,
    const float* __restrict__ emb_o,
    const int*   __restrict__ iword,
    const int*   __restrict__ owords,
    const int*   __restrict__ nwords,
    float*       __restrict__ out)
{
    const int b    = blockIdx.x;
    const int tid  = threadIdx.x;
    const int lane = tid & 31;
    const int w    = tid >> 5;           // 8 warps

    __shared__ float4 s_iv[32];
    __shared__ int    s_idx[NROWS_PAD];  // [0,CCTX): pos; [CCTX,NROWS): neg; pad: 0
    __shared__ float  s_warp[8];
    __shared__ int    s_last;
    __shared__ float  s_red[256];

    if (tid < 32) {
        const float4* ivrow = reinterpret_cast<const float4*>(
            emb_i + (long long)iword[b] * DIM);
        s_iv[tid] = __ldg(&ivrow[tid]);
    }
    if (tid < NROWS_PAD) {
        int v = 0;
        if (tid < CCTX)        v = __ldg(&owords[b * CCTX + tid]);
        else if (tid < NROWS)  v = __ldg(&nwords[b * NNEG + (tid - CCTX)]);
        s_idx[tid] = v;
    }
    __syncthreads();

    const float4 iv = s_iv[lane];        // lane l owns elements [4l, 4l+4)

    float acc = 0.0f;

    // Depth-2 software pipeline over 7 branch-free ILP-4 iterations.
    // Rows of iteration j (for this warp): w + 32*j + {0,8,16,24}.
    float4 cur[4], nxt[4];

    #pragma unroll
    for (int u = 0; u < 4; u++) {
        const int idx = s_idx[w + 8 * u];
        cur[u] = __ldg(&reinterpret_cast<const float4*>(
                     emb_o + (long long)idx * DIM)[lane]);
    }

    #pragma unroll
    for (int j = 0; j < NITER; j++) {
        const int r0 = w + 32 * j;

        // Issue next iteration's loads BEFORE reducing this one.
        if (j + 1 < NITER) {
            #pragma unroll
            for (int u = 0; u < 4; u++) {
                const int idx = s_idx[r0 + 32 + 8 * u];
                nxt[u] = __ldg(&reinterpret_cast<const float4*>(
                             emb_o + (long long)idx * DIM)[lane]);
            }
        }

        float d[4];
        #pragma unroll
        for (int u = 0; u < 4; u++)
            d[u] = cur[u].x * iv.x + cur[u].y * iv.y +
                   cur[u].z * iv.z + cur[u].w * iv.w;

        // 4 independent butterfly chains, interleaved; next loads in flight.
        #pragma unroll
        for (int o = 16; o > 0; o >>= 1) {
            #pragma unroll
            for (int u = 0; u < 4; u++)
                d[u] += __shfl_xor_sync(0xffffffffu, d[u], o);
        }

        #pragma unroll
        for (int u = 0; u < 4; u++) {
            const int r = r0 + 8 * u;
            const float sgn  = (r < CCTX)  ? 1.0f : -1.0f;
            const float mask = (r < NROWS) ? 1.0f : 0.0f;
            acc += mask * log_sigmoid(sgn * d[u]);
        }

        #pragma unroll
        for (int u = 0; u < 4; u++) cur[u] = nxt[u];
    }

    if (lane == 0) s_warp[w] = acc;
    __syncthreads();

    if (tid == 0) {
        float s = 0.0f;
        #pragma unroll
        for (int i = 0; i < 8; i++) s += s_warp[i];
        g_partials[b] = s * (1.0f / (float)CCTX);
    }

    // ---- last-block-done final reduction (deterministic fixed-order sum) ----
    __threadfence();
    if (tid == 0) {
        const unsigned int prev = atomicAdd(&g_done, 1u);
        s_last = (prev == (unsigned int)(BATCH - 1)) ? 1 : 0;
    }
    __syncthreads();

    if (s_last) {
        // 256 threads x 16 strided partials, fixed order. __ldcg: bypass L1
        // so replay N's tail block can't see replay N-1's cached lines.
        float v = 0.0f;
        #pragma unroll
        for (int k = 0; k < BATCH / 256; k++)
            v += __ldcg(&g_partials[tid + k * 256]);
        s_red[tid] = v;
        __syncthreads();
        #pragma unroll
        for (int o = 128; o > 0; o >>= 1) {
            if (tid < o) s_red[tid] += s_red[tid + o];
            __syncthreads();
        }
        if (tid == 0) {
            out[0] = -s_red[0] * (1.0f / (float)BATCH);
            g_done = 0;              // reset for next graph replay
        }
    }
}

extern "C" void kernel_launch(void* const* d_in, const int* in_sizes, int n_in,
                              void* d_out, int out_size)
{
    const float* emb_i  = (const float*)d_in[0];
    const float* emb_o  = (const float*)d_in[1];
    const int*   iword  = (const int*)  d_in[2];
    const int*   owords = (const int*)  d_in[3];
    const int*   nwords = (const int*)  d_in[4];
    float* out = (float*)d_out;

    sgns_fused_kernel<<<BATCH, 256>>>(emb_i, emb_o, iword, owords, nwords, out);
}

// round 14
// speedup vs baseline: 1.3467x; 1.0564x over previous
#include <cuda_runtime.h>
#include <math.h>

// SGNS loss (VOCAB=100000, D=128, B=4096, C=10, N_NEGS=20), single fused kernel.
// Row ownership: 8 lanes per row, 4 rows per warp per phase -> 3 SHFLs reduce
// all 4 rows at once (offsets 4,2,1), vs 5 SHFLs per row previously.

#define BATCH 4096
#define CCTX 10
#define NNEG 200
#define NROWS 210        // 10 positives + 200 negatives
#define NROWS_PAD 224    // 7 phases * 8 warps * 4 rows (pad rows: dummy idx 0)
#define NPHASE 7
#define DIM 128

__device__ float        g_partials[BATCH];
__device__ unsigned int g_done;      // zero-init at load; reset by tail block

__device__ __forceinline__ float log_sigmoid(float x) {
    // stable: min(x,0) - log(1 + exp(-|x|)); log arg in (1,2] -> __logf ok
    return fminf(x, 0.0f) - __logf(1.0f + __expf(-fabsf(x)));
}

__global__ __launch_bounds__(256) void sgns_fused_kernel(
    const float* __restrict__ emb_i,
    const float* __restrict__ emb_o,
    const int*   __restrict__ iword,
    const int*   __restrict__ owords,
    const int*   __restrict__ nwords,
    float*       __restrict__ out)
{
    const int b    = blockIdx.x;
    const int tid  = threadIdx.x;
    const int lane = tid & 31;
    const int w    = tid >> 5;            // 8 warps
    const int grp  = lane >> 3;           // 0..3 : which of 4 rows this lane serves
    const int lg   = lane & 7;            // 0..7 : position within row group

    __shared__ float4 s_iv[32];
    __shared__ int    s_idx[NROWS_PAD];   // [0,CCTX): pos; [CCTX,NROWS): neg; pad: 0
    __shared__ float  s_warp[8];
    __shared__ int    s_last;
    __shared__ float  s_red[256];

    if (tid < 32) {
        const float4* ivrow = reinterpret_cast<const float4*>(
            emb_i + (long long)iword[b] * DIM);
        s_iv[tid] = __ldg(&ivrow[tid]);
    }
    if (tid < NROWS_PAD) {
        int v = 0;
        if (tid < CCTX)        v = __ldg(&owords[b * CCTX + tid]);
        else if (tid < NROWS)  v = __ldg(&nwords[b * NNEG + (tid - CCTX)]);
        s_idx[tid] = v;
    }
    __syncthreads();

    // Each lane's 4 iv chunks: float4 positions lg + 8k, k=0..3.
    float4 iv4[4];
    #pragma unroll
    for (int k = 0; k < 4; k++) iv4[k] = s_iv[lg + 8 * k];

    float acc = 0.0f;

    // Phase j, warp w handles rows 32*j + 4*w + {0,1,2,3}; this lane's row is
    // chosen by grp. Lane loads 4 float4 chunks (contiguous per instruction:
    // 8 lanes x 16B = one 128B sector per group per k).
    float4 cur[4], nxt[4];

    {
        const int idx = s_idx[4 * w + grp];
        const float4* rp = reinterpret_cast<const float4*>(
            emb_o + (long long)idx * DIM);
        #pragma unroll
        for (int k = 0; k < 4; k++) cur[k] = __ldg(&rp[lg + 8 * k]);
    }

    #pragma unroll
    for (int j = 0; j < NPHASE; j++) {
        // Prefetch next phase's chunks before reducing this one.
        if (j + 1 < NPHASE) {
            const int idx = s_idx[32 * (j + 1) + 4 * w + grp];
            const float4* rp = reinterpret_cast<const float4*>(
                emb_o + (long long)idx * DIM);
            #pragma unroll
            for (int k = 0; k < 4; k++) nxt[k] = __ldg(&rp[lg + 8 * k]);
        }

        // Per-lane partial dot over 16 elements (two trees for ILP).
        float p0 = cur[0].x * iv4[0].x + cur[0].y * iv4[0].y +
                   cur[0].z * iv4[0].z + cur[0].w * iv4[0].w;
        float p1 = cur[1].x * iv4[1].x + cur[1].y * iv4[1].y +
                   cur[1].z * iv4[1].z + cur[1].w * iv4[1].w;
        p0 += cur[2].x * iv4[2].x + cur[2].y * iv4[2].y +
              cur[2].z * iv4[2].z + cur[2].w * iv4[2].w;
        p1 += cur[3].x * iv4[3].x + cur[3].y * iv4[3].y +
              cur[3].z * iv4[3].z + cur[3].w * iv4[3].w;
        float d = p0 + p1;

        // One butterfly reduces all 4 rows at once (within 8-lane groups).
        d += __shfl_xor_sync(0xffffffffu, d, 4);
        d += __shfl_xor_sync(0xffffffffu, d, 2);
        d += __shfl_xor_sync(0xffffffffu, d, 1);

        const int r = 32 * j + 4 * w + grp;
        const float sgn  = (r < CCTX)  ? 1.0f : -1.0f;
        const float mask = (r < NROWS) ? 1.0f : 0.0f;
        acc += mask * log_sigmoid(sgn * d);   // identical across the 8 lanes of grp

        #pragma unroll
        for (int k = 0; k < 4; k++) cur[k] = nxt[k];
    }

    // Warp total: each row's contribution appears 8x (once per lane in group).
    #pragma unroll
    for (int o = 16; o > 0; o >>= 1)
        acc += __shfl_xor_sync(0xffffffffu, acc, o);
    if (lane == 0) s_warp[w] = acc * 0.125f;   // exact /8
    __syncthreads();

    if (tid == 0) {
        float s = 0.0f;
        #pragma unroll
        for (int i = 0; i < 8; i++) s += s_warp[i];
        g_partials[b] = s * (1.0f / (float)CCTX);
    }

    // ---- last-block-done final reduction (deterministic fixed-order sum) ----
    __threadfence();
    if (tid == 0) {
        const unsigned int prev = atomicAdd(&g_done, 1u);
        s_last = (prev == (unsigned int)(BATCH - 1)) ? 1 : 0;
    }
    __syncthreads();

    if (s_last) {
        // __ldcg: bypass L1 so replay N's tail block can't see stale lines.
        float v = 0.0f;
        #pragma unroll
        for (int k = 0; k < BATCH / 256; k++)
            v += __ldcg(&g_partials[tid + k * 256]);
        s_red[tid] = v;
        __syncthreads();
        #pragma unroll
        for (int o = 128; o > 0; o >>= 1) {
            if (tid < o) s_red[tid] += s_red[tid + o];
            __syncthreads();
        }
        if (tid == 0) {
            out[0] = -s_red[0] * (1.0f / (float)BATCH);
            g_done = 0;              // reset for next graph replay
        }
    }
}

extern "C" void kernel_launch(void* const* d_in, const int* in_sizes, int n_in,
                              void* d_out, int out_size)
{
    const float* emb_i  = (const float*)d_in[0];
    const float* emb_o  = (const float*)d_in[1];
    const int*   iword  = (const int*)  d_in[2];
    const int*   owords = (const int*)  d_in[3];
    const int*   nwords = (const int*)  d_in[4];
    float* out = (float*)d_out;

    sgns_fused_kernel<<<BATCH, 256>>>(emb_i, emb_o, iword, owords, nwords, out);
}